// round 15
// baseline (speedup 1.0000x reference)
#include <cuda_runtime.h>

#define TILE 64
#define TRS  68   // transposed-tile row stride in floats (64 + 4 pad)

__device__ __forceinline__ float frcp(float x) {
    float r; asm("rcp.approx.f32 %0, %1;" : "=f"(r) : "f"(x)); return r;
}

template <bool FULL>
__global__ __launch_bounds__(256, 4) void pair_kernel(float* __restrict__ out,
                                                      const float* __restrict__ boxes,
                                                      int nb, int T, int nblk) {
    const int tid = threadIdx.x;

    // SoA shared layout: [0,64) = i-tile, [64,128) = j-tile (16B aligned)
    __shared__ __align__(16) float s_cx[128];
    __shared__ __align__(16) float s_cy[128];
    __shared__ __align__(16) float s_c [128];
    __shared__ __align__(16) float s_s [128];
    __shared__ __align__(16) float s_hx[128];
    __shared__ __align__(16) float s_hy[128];
    // Transposed result tile (row j, col i), stride 68, XOR-swizzled columns
    __shared__ __align__(16) float s_tr[TILE * TRS];

    const int tx = tid & 15;   // j sub-tile (4 boxes)
    const int ty = tid >> 4;   // i sub-tile (4 boxes)
    const int ib = ty * 4;
    const int jb = tx * 4;

    // Persistent loop over upper-triangular tile pairs
    for (int b = blockIdx.x; b < nblk; b += gridDim.x) {
        // Map linear index -> (r, c), r <= c
        float Tf = (float)T;
        int r = (int)floorf(((2.0f * Tf + 1.0f) -
                    sqrtf((2.0f * Tf + 1.0f) * (2.0f * Tf + 1.0f) - 8.0f * (float)b)) * 0.5f);
        if (r < 0) r = 0;
        if (r > T - 1) r = T - 1;
        while (r > 0 && r * T - (r * (r - 1)) / 2 > b) --r;
        while ((r + 1) * T - ((r + 1) * r) / 2 <= b) ++r;
        const int c = r + (b - (r * T - (r * (r - 1)) / 2));

        const int i0 = r * TILE;
        const int j0 = c * TILE;

        // Fused prep: threads 0..127 each convert one box (i-tile then j-tile).
        // Safe vs. previous iteration: only s_tr is read after the second sync,
        // and these writes touch the param arrays only.
        if (tid < 128) {
            const int which = tid >> 6;          // 0 -> i tile, 1 -> j tile
            const int slot  = tid & 63;
            const int gidx  = (which ? j0 : i0) + slot;
            float cx = 0.0f, cy = 0.0f, hx = 0.5f, hy = 0.5f, cc = 1.0f, ss = 0.0f;
            if (FULL || gidx < nb) {
                const float* bp = boxes + (size_t)gidx * 5;
                cx = bp[0];
                cy = bp[1];
                hx = bp[2] * 0.5f;
                hy = bp[3] * 0.5f;
                __sincosf(bp[4], &ss, &cc);
            }
            s_cx[tid] = cx; s_cy[tid] = cy;
            s_c [tid] = cc; s_s [tid] = ss;
            s_hx[tid] = hx; s_hy[tid] = hy;
        }
        __syncthreads();

        // Hoist the 4 j-box params via LDS.128 from SoA
        float4 CXJ = *reinterpret_cast<const float4*>(&s_cx[64 + jb]);
        float4 CYJ = *reinterpret_cast<const float4*>(&s_cy[64 + jb]);
        float4 CJ4 = *reinterpret_cast<const float4*>(&s_c [64 + jb]);
        float4 SJ4 = *reinterpret_cast<const float4*>(&s_s [64 + jb]);
        float4 HXJ = *reinterpret_cast<const float4*>(&s_hx[64 + jb]);
        float4 HYJ = *reinterpret_cast<const float4*>(&s_hy[64 + jb]);
        const float* cxj = &CXJ.x;
        const float* cyj = &CYJ.x;
        const float* cj  = &CJ4.x;
        const float* sj  = &SJ4.x;
        const float* hxj = &HXJ.x;
        const float* hyj = &HYJ.x;

        const bool diagblk = (i0 == j0);

        float4 res[4];   // res[ii] = row of 4 results

#pragma unroll
        for (int ii = 0; ii < 4; ii++) {
            const float cxi = s_cx[ib + ii];
            const float cyi = s_cy[ib + ii];
            const float ci  = s_c [ib + ii];
            const float si  = s_s [ib + ii];
            const float hxi = s_hx[ib + ii];
            const float hyi = s_hy[ib + ii];

            float* resf = &res[ii].x;
#pragma unroll
            for (int jj = 0; jj < 4; jj++) {
                const float dx = cxj[jj] - cxi;
                const float dy = cyj[jj] - cyi;
                const float cd = fmaf(ci, cj[jj], si * sj[jj]);
                const float sd = fmaf(si, cj[jj], -(ci * sj[jj]));
                const float A  = fabsf(cd);
                const float Bb = fabsf(sd);
                const float q1 = fmaf(dx, ci, -(dy * si));
                const float q2 = fmaf(dx, si, dy * ci);
                const float q3 = fmaf(dx, cj[jj], -(dy * sj[jj]));
                const float q4 = fmaf(dx, sj[jj], dy * cj[jj]);
                const float r21 = fmaf(hxj[jj], A,  hyj[jj] * Bb);
                const float r22 = fmaf(hxj[jj], Bb, hyj[jj] * A);
                const float r23 = fmaf(hxi,     A,  hyi * Bb);
                const float r24 = fmaf(hxi,     Bb, hyi * A);

                // Per-axis: a = r1+r2, t = max(|r1-r2|, |q|), g = (a-t)/(a+t).
                // g monotone-decreasing in u = t/a, so min_k g_k <-> max_k u_k.
                // u via rcp (MUFU is far from capacity); one more rcp for g.
                const float a1 = hxi     + r21, t1 = fmaxf(fabsf(hxi     - r21), fabsf(q1));
                const float a2 = hyi     + r22, t2 = fmaxf(fabsf(hyi     - r22), fabsf(q2));
                const float a3 = hxj[jj] + r23, t3 = fmaxf(fabsf(hxj[jj] - r23), fabsf(q3));
                const float a4 = hyj[jj] + r24, t4 = fmaxf(fabsf(hyj[jj] - r24), fabsf(q4));

                const float u1 = t1 * frcp(a1);
                const float u2 = t2 * frcp(a2);
                const float u3 = t3 * frcp(a3);
                const float u4 = t4 * frcp(a4);
                const float u  = fmaxf(fmaxf(u1, u2), fmaxf(u3, u4));

                resf[jj] = fmaxf((1.0f - u) * frcp(1.0f + u), 0.0f);
            }
        }

        // Diagonal fixup: gi==gj inside a micro-tile requires tx==ty, ii==jj
        if (diagblk && tx == ty) {
            res[0].x = 0.0f; res[1].y = 0.0f; res[2].z = 0.0f; res[3].w = 0.0f;
        }

        // ---- Stage transposed tile into smem (register transpose + STS.128) ----
        {
            const float* r0 = &res[0].x;
            const float* r1 = &res[1].x;
            const float* r2 = &res[2].x;
            const float* r3 = &res[3].x;
            const int colbase = (4 * ty) ^ ((tx & 7) << 2);
#pragma unroll
            for (int jj = 0; jj < 4; jj++) {
                float4 v = make_float4(r0[jj], r1[jj], r2[jj], r3[jj]);
                *reinterpret_cast<float4*>(&s_tr[(4 * tx + jj) * TRS + colbase]) = v;
            }
        }

        // ---- Direct stores: rows i0+ib.., cols j0+jb.. (coalesced) ----
        const int gjbase = j0 + jb;
#pragma unroll
        for (int ii = 0; ii < 4; ii++) {
            const int gi = i0 + ib + ii;
            if (FULL) {
                *reinterpret_cast<float4*>(&out[(size_t)gi * nb + gjbase]) = res[ii];
            } else {
                if (gi < nb && gjbase + 3 < nb) {
                    *reinterpret_cast<float4*>(&out[(size_t)gi * nb + gjbase]) = res[ii];
                } else if (gi < nb) {
                    const float* resf = &res[ii].x;
#pragma unroll
                    for (int jj = 0; jj < 4; jj++)
                        if (gjbase + jj < nb) out[(size_t)gi * nb + gjbase + jj] = resf[jj];
                }
            }
        }

        __syncthreads();

        // ---- Mirror stores from smem (coalesced rows of the transposed tile) ----
        if (!diagblk) {
            const int g4 = tid & 15;           // 16 float4 groups per row
            const int rbase = tid >> 4;        // 16 rows per pass
#pragma unroll
            for (int k = 0; k < 4; k++) {
                const int rho = rbase + 16 * k;            // row within j-tile
                const int colbase = (4 * g4) ^ (((rho >> 2) & 7) << 2);
                float4 v = *reinterpret_cast<const float4*>(&s_tr[rho * TRS + colbase]);
                const int gj = j0 + rho;
                const int gib = i0 + 4 * g4;
                if (FULL) {
                    *reinterpret_cast<float4*>(&out[(size_t)gj * nb + gib]) = v;
                } else {
                    if (gj < nb && gib + 3 < nb) {
                        *reinterpret_cast<float4*>(&out[(size_t)gj * nb + gib]) = v;
                    } else if (gj < nb) {
                        const float* vf = &v.x;
#pragma unroll
                        for (int ii = 0; ii < 4; ii++)
                            if (gib + ii < nb) out[(size_t)gj * nb + gib + ii] = vf[ii];
                    }
                }
            }
        }
        // No extra sync needed: next iteration's prep writes param arrays only,
        // and its s_tr writes are gated by the post-prep sync above.
    }
}

extern "C" void kernel_launch(void* const* d_in, const int* in_sizes, int n_in,
                              void* d_out, int out_size) {
    const float* boxes = (const float*)d_in[0];
    float* out = (float*)d_out;
    const int nb = in_sizes[0] / 5;

    const int T = (nb + TILE - 1) / TILE;
    const int nblk = T * (T + 1) / 2;
    const int grid = (nblk < 592) ? nblk : 592;   // 148 SMs x 4 resident blocks
    if (nb % TILE == 0)
        pair_kernel<true><<<grid, 256>>>(out, boxes, nb, T, nblk);
    else
        pair_kernel<false><<<grid, 256>>>(out, boxes, nb, T, nblk);
}

// round 16
// speedup vs baseline: 1.1209x; 1.1209x over previous
#include <cuda_runtime.h>

#define TILE 64
#define TRS  68   // transposed-tile row stride in floats (64 + 4 pad)

__device__ __forceinline__ float frcp(float x) {
    float r; asm("rcp.approx.f32 %0, %1;" : "=f"(r) : "f"(x)); return r;
}

template <bool FULL>
__global__ __launch_bounds__(256, 4) void pair_kernel(float* __restrict__ out,
                                                      const float* __restrict__ boxes,
                                                      int nb, int T) {
    // Map linear block index -> upper-triangular tile pair (r <= c)
    const int b = blockIdx.x;
    float Tf = (float)T;
    int r = (int)floorf(((2.0f * Tf + 1.0f) -
                sqrtf((2.0f * Tf + 1.0f) * (2.0f * Tf + 1.0f) - 8.0f * (float)b)) * 0.5f);
    if (r < 0) r = 0;
    if (r > T - 1) r = T - 1;
    while (r > 0 && r * T - (r * (r - 1)) / 2 > b) --r;
    while ((r + 1) * T - ((r + 1) * r) / 2 <= b) ++r;
    const int c = r + (b - (r * T - (r * (r - 1)) / 2));

    const int i0 = r * TILE;
    const int j0 = c * TILE;
    const int tid = threadIdx.x;

    // SoA shared layout: [0,64) = i-tile, [64,128) = j-tile (16B aligned)
    __shared__ __align__(16) float s_cx[128];
    __shared__ __align__(16) float s_cy[128];
    __shared__ __align__(16) float s_c [128];
    __shared__ __align__(16) float s_s [128];
    __shared__ __align__(16) float s_hx[128];
    __shared__ __align__(16) float s_hy[128];
    // Transposed result tile (row j, col i), stride 68, XOR-swizzled columns
    __shared__ __align__(16) float s_tr[TILE * TRS];

    // Fused prep: threads 0..127 each convert one box (i-tile then j-tile)
    if (tid < 128) {
        const int which = tid >> 6;          // 0 -> i tile, 1 -> j tile
        const int slot  = tid & 63;
        const int gidx  = (which ? j0 : i0) + slot;
        float cx = 0.0f, cy = 0.0f, hx = 0.5f, hy = 0.5f, cc = 1.0f, ss = 0.0f;
        if (FULL || gidx < nb) {
            const float* bp = boxes + (size_t)gidx * 5;
            cx = bp[0];
            cy = bp[1];
            hx = bp[2] * 0.5f;
            hy = bp[3] * 0.5f;
            __sincosf(bp[4], &ss, &cc);
        }
        s_cx[tid] = cx; s_cy[tid] = cy;
        s_c [tid] = cc; s_s [tid] = ss;
        s_hx[tid] = hx; s_hy[tid] = hy;
    }
    __syncthreads();

    const int tx = tid & 15;   // j sub-tile (4 boxes)
    const int ty = tid >> 4;   // i sub-tile (4 boxes)
    const int ib = ty * 4;
    const int jb = tx * 4;

    // Hoist the 4 j-box params via LDS.128 from SoA
    float4 CXJ = *reinterpret_cast<const float4*>(&s_cx[64 + jb]);
    float4 CYJ = *reinterpret_cast<const float4*>(&s_cy[64 + jb]);
    float4 CJ4 = *reinterpret_cast<const float4*>(&s_c [64 + jb]);
    float4 SJ4 = *reinterpret_cast<const float4*>(&s_s [64 + jb]);
    float4 HXJ = *reinterpret_cast<const float4*>(&s_hx[64 + jb]);
    float4 HYJ = *reinterpret_cast<const float4*>(&s_hy[64 + jb]);
    const float* cxj = &CXJ.x;
    const float* cyj = &CYJ.x;
    const float* cj  = &CJ4.x;
    const float* sj  = &SJ4.x;
    const float* hxj = &HXJ.x;
    const float* hyj = &HYJ.x;

    const bool diagblk = (i0 == j0);

    float4 res[4];   // res[ii] = row of 4 results

#pragma unroll
    for (int ii = 0; ii < 4; ii++) {
        const float cxi = s_cx[ib + ii];
        const float cyi = s_cy[ib + ii];
        const float ci  = s_c [ib + ii];
        const float si  = s_s [ib + ii];
        const float hxi = s_hx[ib + ii];
        const float hyi = s_hy[ib + ii];

        float* resf = &res[ii].x;
#pragma unroll
        for (int jj = 0; jj < 4; jj++) {
            const float dx = cxj[jj] - cxi;
            const float dy = cyj[jj] - cyi;
            const float cd = fmaf(ci, cj[jj], si * sj[jj]);
            const float sd = fmaf(si, cj[jj], -(ci * sj[jj]));
            const float A  = fabsf(cd);
            const float Bb = fabsf(sd);
            const float q1 = fmaf(dx, ci, -(dy * si));
            const float q2 = fmaf(dx, si, dy * ci);
            const float q3 = fmaf(dx, cj[jj], -(dy * sj[jj]));
            const float q4 = fmaf(dx, sj[jj], dy * cj[jj]);
            const float r21 = fmaf(hxj[jj], A,  hyj[jj] * Bb);
            const float r22 = fmaf(hxj[jj], Bb, hyj[jj] * A);
            const float r23 = fmaf(hxi,     A,  hyi * Bb);
            const float r24 = fmaf(hxi,     Bb, hyi * A);

            // Per-axis: a = r1+r2, t = max(|r1-r2|, |q|), g = (a-t)/(a+t).
            // g monotone-decreasing in u = t/a, so min_k g_k <-> max_k u_k.
            const float a1 = hxi     + r21, t1 = fmaxf(fabsf(hxi     - r21), fabsf(q1));
            const float a2 = hyi     + r22, t2 = fmaxf(fabsf(hyi     - r22), fabsf(q2));
            const float a3 = hxj[jj] + r23, t3 = fmaxf(fabsf(hxj[jj] - r23), fabsf(q3));
            const float a4 = hyj[jj] + r24, t4 = fmaxf(fabsf(hyj[jj] - r24), fabsf(q4));

            const float u1 = t1 * frcp(a1);
            const float u2 = t2 * frcp(a2);
            const float u3 = t3 * frcp(a3);
            const float u4 = t4 * frcp(a4);
            const float u  = fmaxf(fmaxf(u1, u2), fmaxf(u3, u4));

            resf[jj] = fmaxf((1.0f - u) * frcp(1.0f + u), 0.0f);
        }
    }

    // Diagonal fixup: gi==gj inside a 4x4 micro-tile requires tx==ty and ii==jj
    if (diagblk && tx == ty) {
        res[0].x = 0.0f; res[1].y = 0.0f; res[2].z = 0.0f; res[3].w = 0.0f;
    }

    // ---- Stage transposed tile into smem (register 4x4 transpose + STS.128) ----
    {
        const float* r0 = &res[0].x;
        const float* r1 = &res[1].x;
        const float* r2 = &res[2].x;
        const float* r3 = &res[3].x;
        const int colbase = (4 * ty) ^ ((tx & 7) << 2);
#pragma unroll
        for (int jj = 0; jj < 4; jj++) {
            float4 v = make_float4(r0[jj], r1[jj], r2[jj], r3[jj]);
            *reinterpret_cast<float4*>(&s_tr[(4 * tx + jj) * TRS + colbase]) = v;
        }
    }

    // ---- Direct stores: rows i0+ib.., cols j0+jb.. (coalesced) ----
    const int gjbase = j0 + jb;
#pragma unroll
    for (int ii = 0; ii < 4; ii++) {
        const int gi = i0 + ib + ii;
        if (FULL) {
            *reinterpret_cast<float4*>(&out[(size_t)gi * nb + gjbase]) = res[ii];
        } else {
            if (gi < nb && gjbase + 3 < nb) {
                *reinterpret_cast<float4*>(&out[(size_t)gi * nb + gjbase]) = res[ii];
            } else if (gi < nb) {
                const float* resf = &res[ii].x;
#pragma unroll
                for (int jj = 0; jj < 4; jj++)
                    if (gjbase + jj < nb) out[(size_t)gi * nb + gjbase + jj] = resf[jj];
            }
        }
    }

    __syncthreads();

    // ---- Mirror stores from smem (coalesced rows of the transposed tile) ----
    if (!diagblk) {
        const int g4 = tid & 15;           // 16 float4 groups per row
        const int rbase = tid >> 4;        // 16 rows per pass
#pragma unroll
        for (int k = 0; k < 4; k++) {
            const int rho = rbase + 16 * k;            // row within j-tile
            const int colbase = (4 * g4) ^ (((rho >> 2) & 7) << 2);
            float4 v = *reinterpret_cast<const float4*>(&s_tr[rho * TRS + colbase]);
            const int gj = j0 + rho;
            const int gib = i0 + 4 * g4;
            if (FULL) {
                *reinterpret_cast<float4*>(&out[(size_t)gj * nb + gib]) = v;
            } else {
                if (gj < nb && gib + 3 < nb) {
                    *reinterpret_cast<float4*>(&out[(size_t)gj * nb + gib]) = v;
                } else if (gj < nb) {
                    const float* vf = &v.x;
#pragma unroll
                    for (int ii = 0; ii < 4; ii++)
                        if (gib + ii < nb) out[(size_t)gj * nb + gib + ii] = vf[ii];
                }
            }
        }
    }
}

extern "C" void kernel_launch(void* const* d_in, const int* in_sizes, int n_in,
                              void* d_out, int out_size) {
    const float* boxes = (const float*)d_in[0];
    float* out = (float*)d_out;
    const int nb = in_sizes[0] / 5;

    const int T = (nb + TILE - 1) / TILE;
    const int nblk = T * (T + 1) / 2;
    if (nb % TILE == 0)
        pair_kernel<true><<<nblk, 256>>>(out, boxes, nb, T);
    else
        pair_kernel<false><<<nblk, 256>>>(out, boxes, nb, T);
}

// round 17
// speedup vs baseline: 1.3857x; 1.2363x over previous
#include <cuda_runtime.h>

#define TILE 64
#define TRS  68   // transposed-tile row stride in floats (64 + 4 pad)

// NB > 0: compile-time box count (fast path, strides fold to constants).
// NB == 0: runtime nb (generic path).
template <bool FULL, int NB>
__global__ __launch_bounds__(256, 4) void pair_kernel(float* __restrict__ out,
                                                      const float* __restrict__ boxes,
                                                      int nb_rt, int T) {
    const int nb = (NB > 0) ? NB : nb_rt;

    // Map linear block index -> upper-triangular tile pair (r <= c)
    const int b = blockIdx.x;
    float Tf = (float)T;
    int r = (int)floorf(((2.0f * Tf + 1.0f) -
                sqrtf((2.0f * Tf + 1.0f) * (2.0f * Tf + 1.0f) - 8.0f * (float)b)) * 0.5f);
    if (r < 0) r = 0;
    if (r > T - 1) r = T - 1;
    while (r > 0 && r * T - (r * (r - 1)) / 2 > b) --r;
    while ((r + 1) * T - ((r + 1) * r) / 2 <= b) ++r;
    const int c = r + (b - (r * T - (r * (r - 1)) / 2));

    const int i0 = r * TILE;
    const int j0 = c * TILE;
    const int tid = threadIdx.x;

    // SoA shared layout: [0,64) = i-tile, [64,128) = j-tile (16B aligned)
    __shared__ __align__(16) float s_cx[128];
    __shared__ __align__(16) float s_cy[128];
    __shared__ __align__(16) float s_c [128];
    __shared__ __align__(16) float s_s [128];
    __shared__ __align__(16) float s_hx[128];
    __shared__ __align__(16) float s_hy[128];
    // Transposed result tile (row j, col i), stride 68, XOR-swizzled columns
    __shared__ __align__(16) float s_tr[TILE * TRS];

    // Fused prep: threads 0..127 each convert one box (i-tile then j-tile)
    if (tid < 128) {
        const int which = tid >> 6;          // 0 -> i tile, 1 -> j tile
        const int slot  = tid & 63;
        const int gidx  = (which ? j0 : i0) + slot;
        float cx = 0.0f, cy = 0.0f, hx = 0.5f, hy = 0.5f, cc = 1.0f, ss = 0.0f;
        if (FULL || gidx < nb) {
            const float* bp = boxes + (size_t)gidx * 5;
            cx = bp[0];
            cy = bp[1];
            hx = bp[2] * 0.5f;
            hy = bp[3] * 0.5f;
            __sincosf(bp[4], &ss, &cc);
        }
        s_cx[tid] = cx; s_cy[tid] = cy;
        s_c [tid] = cc; s_s [tid] = ss;
        s_hx[tid] = hx; s_hy[tid] = hy;
    }
    __syncthreads();

    const int tx = tid & 15;   // j sub-tile (4 boxes)
    const int ty = tid >> 4;   // i sub-tile (4 boxes)
    const int ib = ty * 4;
    const int jb = tx * 4;

    // Hoist the 4 j-box params via LDS.128 from SoA
    float4 CXJ = *reinterpret_cast<const float4*>(&s_cx[64 + jb]);
    float4 CYJ = *reinterpret_cast<const float4*>(&s_cy[64 + jb]);
    float4 CJ4 = *reinterpret_cast<const float4*>(&s_c [64 + jb]);
    float4 SJ4 = *reinterpret_cast<const float4*>(&s_s [64 + jb]);
    float4 HXJ = *reinterpret_cast<const float4*>(&s_hx[64 + jb]);
    float4 HYJ = *reinterpret_cast<const float4*>(&s_hy[64 + jb]);
    const float* cxj = &CXJ.x;
    const float* cyj = &CYJ.x;
    const float* cj  = &CJ4.x;
    const float* sj  = &SJ4.x;
    const float* hxj = &HXJ.x;
    const float* hyj = &HYJ.x;

    const bool diagblk = (i0 == j0);

    float4 res[4];   // res[ii] = row of 4 results

#pragma unroll
    for (int ii = 0; ii < 4; ii++) {
        const float cxi = s_cx[ib + ii];
        const float cyi = s_cy[ib + ii];
        const float ci  = s_c [ib + ii];
        const float si  = s_s [ib + ii];
        const float hxi = s_hx[ib + ii];
        const float hyi = s_hy[ib + ii];

        float* resf = &res[ii].x;
#pragma unroll
        for (int jj = 0; jj < 4; jj++) {
            const float dx = cxj[jj] - cxi;
            const float dy = cyj[jj] - cyi;
            const float cd = fmaf(ci, cj[jj], si * sj[jj]);
            const float sd = fmaf(si, cj[jj], -(ci * sj[jj]));
            const float A  = fabsf(cd);
            const float Bb = fabsf(sd);
            const float q1 = fmaf(dx, ci, -(dy * si));
            const float q2 = fmaf(dx, si, dy * ci);
            const float q3 = fmaf(dx, cj[jj], -(dy * sj[jj]));
            const float q4 = fmaf(dx, sj[jj], dy * cj[jj]);
            const float r21 = fmaf(hxj[jj], A,  hyj[jj] * Bb);
            const float r22 = fmaf(hxj[jj], Bb, hyj[jj] * A);
            const float r23 = fmaf(hxi,     A,  hyi * Bb);
            const float r24 = fmaf(hxi,     Bb, hyi * A);

            // Per-axis closed form: g_k = (a_k - t_k)/(a_k + t_k),
            //   a_k = r1+r2,  t_k = max(|r1-r2|, |q_k|).
            // min_k g_k = axis with max t_k/a_k; compare via cross-products,
            // single MUFU.RCP per pair.
            const float a1 = hxi     + r21, t1 = fmaxf(fabsf(hxi     - r21), fabsf(q1));
            const float a2 = hyi     + r22, t2 = fmaxf(fabsf(hyi     - r22), fabsf(q2));
            const float a3 = hxj[jj] + r23, t3 = fmaxf(fabsf(hxj[jj] - r23), fabsf(q3));
            const float a4 = hyj[jj] + r24, t4 = fmaxf(fabsf(hyj[jj] - r24), fabsf(q4));

            const bool p12 = t1 * a2 > t2 * a1;
            const float tA = p12 ? t1 : t2;
            const float aA = p12 ? a1 : a2;
            const bool p34 = t3 * a4 > t4 * a3;
            const float tB = p34 ? t3 : t4;
            const float aB = p34 ? a3 : a4;
            const bool pAB = tA * aB > tB * aA;
            const float t = pAB ? tA : tB;
            const float a = pAB ? aA : aB;

            resf[jj] = fmaxf(__fdividef(a - t, a + t), 0.0f);
        }
    }

    // Diagonal fixup: gi==gj inside a 4x4 micro-tile requires tx==ty and ii==jj
    if (diagblk && tx == ty) {
        res[0].x = 0.0f; res[1].y = 0.0f; res[2].z = 0.0f; res[3].w = 0.0f;
    }

    // ---- Stage transposed tile into smem (register 4x4 transpose + STS.128) ----
    {
        const float* r0 = &res[0].x;
        const float* r1 = &res[1].x;
        const float* r2 = &res[2].x;
        const float* r3 = &res[3].x;
        const int colbase = (4 * ty) ^ ((tx & 7) << 2);
#pragma unroll
        for (int jj = 0; jj < 4; jj++) {
            float4 v = make_float4(r0[jj], r1[jj], r2[jj], r3[jj]);
            *reinterpret_cast<float4*>(&s_tr[(4 * tx + jj) * TRS + colbase]) = v;
        }
    }

    // ---- Direct stores: rows i0+ib.., cols j0+jb.. (coalesced) ----
    const int gjbase = j0 + jb;
#pragma unroll
    for (int ii = 0; ii < 4; ii++) {
        const int gi = i0 + ib + ii;
        if (FULL) {
            *reinterpret_cast<float4*>(&out[(size_t)gi * nb + gjbase]) = res[ii];
        } else {
            if (gi < nb && gjbase + 3 < nb) {
                *reinterpret_cast<float4*>(&out[(size_t)gi * nb + gjbase]) = res[ii];
            } else if (gi < nb) {
                const float* resf = &res[ii].x;
#pragma unroll
                for (int jj = 0; jj < 4; jj++)
                    if (gjbase + jj < nb) out[(size_t)gi * nb + gjbase + jj] = resf[jj];
            }
        }
    }

    __syncthreads();

    // ---- Mirror stores from smem (coalesced rows of the transposed tile) ----
    if (!diagblk) {
        const int g4 = tid & 15;           // 16 float4 groups per row
        const int rbase = tid >> 4;        // 16 rows per pass
#pragma unroll
        for (int k = 0; k < 4; k++) {
            const int rho = rbase + 16 * k;            // row within j-tile
            const int colbase = (4 * g4) ^ (((rho >> 2) & 7) << 2);
            float4 v = *reinterpret_cast<const float4*>(&s_tr[rho * TRS + colbase]);
            const int gj = j0 + rho;
            const int gib = i0 + 4 * g4;
            if (FULL) {
                *reinterpret_cast<float4*>(&out[(size_t)gj * nb + gib]) = v;
            } else {
                if (gj < nb && gib + 3 < nb) {
                    *reinterpret_cast<float4*>(&out[(size_t)gj * nb + gib]) = v;
                } else if (gj < nb) {
                    const float* vf = &v.x;
#pragma unroll
                    for (int ii = 0; ii < 4; ii++)
                        if (gib + ii < nb) out[(size_t)gj * nb + gib + ii] = vf[ii];
                }
            }
        }
    }
}

extern "C" void kernel_launch(void* const* d_in, const int* in_sizes, int n_in,
                              void* d_out, int out_size) {
    const float* boxes = (const float*)d_in[0];
    float* out = (float*)d_out;
    const int nb = in_sizes[0] / 5;

    const int T = (nb + TILE - 1) / TILE;
    const int nblk = T * (T + 1) / 2;
    if (nb == 4096)
        pair_kernel<true, 4096><<<nblk, 256>>>(out, boxes, nb, T);
    else if (nb % TILE == 0)
        pair_kernel<true, 0><<<nblk, 256>>>(out, boxes, nb, T);
    else
        pair_kernel<false, 0><<<nblk, 256>>>(out, boxes, nb, T);
}